// round 12
// baseline (speedup 1.0000x reference)
#include <cuda_runtime.h>
#include <cuda_fp16.h>
#include <math.h>
#include <stdint.h>

#define N_CI    2048
#define N_EL    524288          // 8192 * 64
#define KSPLIT  16
#define KQ      512             // K per split
#define KC      32
#define NCH     (KQ / KC)       // 16 chunks
#define CO32_LD 136             // Co tile row stride (floats): bank = 8k+n, conflict-free
#define YN32_LD 36              // yn tile row stride (floats): bank = 4r+c, conflict-free
#define CO32_BUF (KC * CO32_LD)            // 4352 floats
#define YN32_BUF (64 * YN32_LD)            // 2304 floats
#define K3_SMEM  ((2 * CO32_BUF + 2 * YN32_BUF) * 4)   // 53248 bytes

__device__ __align__(16) float g_y[N_EL];
__device__ __align__(16) float g_ynT32[64 * 8192];     // [m][row], tf32-rounded fp32
__device__ __align__(16) float g_part[KSPLIT * N_EL];  // 33.5 MB
__device__ float g_psum[N_CI];
__device__ float g_psq[N_CI];
__device__ float g_stats[2];

__device__ __forceinline__ float gelu_tanh(float v) {
    const float c = 0.7978845608028654f;
    float t = tanhf(c * (v + 0.044715f * v * v * v));
    return 0.5f * v * (1.0f + t);
}

// ===========================================================================
// K1: y[i,l,j] = sum_{k,m} Wi[i,j,k,l,m] * x[i,m,k]; gelu; LN partials.
// ===========================================================================
__global__ void __launch_bounds__(256) k1_capsule(const float* __restrict__ x,
                                                  const float* __restrict__ Wi) {
    __shared__ float4 xs4[64];
    __shared__ float s_sum, s_sq;
    int tid = threadIdx.x;
    int i = blockIdx.x;
    if (tid == 0) { s_sum = 0.f; s_sq = 0.f; }
    {
        int k = tid >> 2, m = tid & 3;
        ((float*)xs4)[tid] = x[(size_t)i * 256 + m * 64 + k];
    }
    __syncthreads();

    int w = tid >> 5, lane = tid & 31;
    int l = lane & 3, kq = lane >> 2;
    const float4* wbase = (const float4*)(Wi + (size_t)i * 65536);
    float ls = 0.f, ls2 = 0.f;

    #pragma unroll 1
    for (int jj = 0; jj < 8; jj += 4) {
        int j0 = w * 8 + jj;
        const float4* wp = wbase + (size_t)j0 * 256 + lane;
        float acc0 = 0.f, acc1 = 0.f, acc2 = 0.f, acc3 = 0.f;
        #pragma unroll
        for (int r = 0; r < 8; r++) {
            float4 xv = xs4[r * 8 + kq];
            float4 w0 = wp[r * 32];
            float4 w1 = wp[r * 32 + 256];
            float4 w2 = wp[r * 32 + 512];
            float4 w3 = wp[r * 32 + 768];
            acc0 = fmaf(w0.x, xv.x, acc0); acc0 = fmaf(w0.y, xv.y, acc0);
            acc0 = fmaf(w0.z, xv.z, acc0); acc0 = fmaf(w0.w, xv.w, acc0);
            acc1 = fmaf(w1.x, xv.x, acc1); acc1 = fmaf(w1.y, xv.y, acc1);
            acc1 = fmaf(w1.z, xv.z, acc1); acc1 = fmaf(w1.w, xv.w, acc1);
            acc2 = fmaf(w2.x, xv.x, acc2); acc2 = fmaf(w2.y, xv.y, acc2);
            acc2 = fmaf(w2.z, xv.z, acc2); acc2 = fmaf(w2.w, xv.w, acc2);
            acc3 = fmaf(w3.x, xv.x, acc3); acc3 = fmaf(w3.y, xv.y, acc3);
            acc3 = fmaf(w3.z, xv.z, acc3); acc3 = fmaf(w3.w, xv.w, acc3);
        }
        acc0 += __shfl_xor_sync(0xffffffffu, acc0, 4);
        acc0 += __shfl_xor_sync(0xffffffffu, acc0, 8);
        acc0 += __shfl_xor_sync(0xffffffffu, acc0, 16);
        acc1 += __shfl_xor_sync(0xffffffffu, acc1, 4);
        acc1 += __shfl_xor_sync(0xffffffffu, acc1, 8);
        acc1 += __shfl_xor_sync(0xffffffffu, acc1, 16);
        acc2 += __shfl_xor_sync(0xffffffffu, acc2, 4);
        acc2 += __shfl_xor_sync(0xffffffffu, acc2, 8);
        acc2 += __shfl_xor_sync(0xffffffffu, acc2, 16);
        acc3 += __shfl_xor_sync(0xffffffffu, acc3, 4);
        acc3 += __shfl_xor_sync(0xffffffffu, acc3, 8);
        acc3 += __shfl_xor_sync(0xffffffffu, acc3, 16);
        float g0 = gelu_tanh(acc0);
        float g1 = gelu_tanh(acc1);
        float g2 = gelu_tanh(acc2);
        float g3 = gelu_tanh(acc3);
        if (lane < 4) {
            float* yp = &g_y[((size_t)i * 4 + l) * 64 + j0];
            yp[0] = g0; yp[1] = g1; yp[2] = g2; yp[3] = g3;
            ls += (g0 + g1) + (g2 + g3);
            ls2 += (g0 * g0 + g1 * g1) + (g2 * g2 + g3 * g3);
        }
    }
    if (lane < 4) {
        atomicAdd(&s_sum, ls);
        atomicAdd(&s_sq, ls2);
    }
    __syncthreads();
    if (tid == 0) { g_psum[i] = s_sum; g_psq[i] = s_sq; }
}

// ===========================================================================
// K2: reduce partials -> mu, rsig (1 CTA, fp64)
// ===========================================================================
__global__ void k2_stats() {
    __shared__ double sh[256], sh2[256];
    int tid = threadIdx.x;
    double a = 0.0, b = 0.0;
    for (int i = tid; i < N_CI; i += 256) {
        a += (double)g_psum[i];
        b += (double)g_psq[i];
    }
    sh[tid] = a; sh2[tid] = b;
    __syncthreads();
    for (int s = 128; s > 0; s >>= 1) {
        if (tid < s) { sh[tid] += sh[tid + s]; sh2[tid] += sh2[tid + s]; }
        __syncthreads();
    }
    if (tid == 0) {
        double mu = sh[0] / (double)N_EL;
        double var = sh2[0] / (double)N_EL - mu * mu;
        g_stats[0] = (float)mu;
        g_stats[1] = (float)(1.0 / sqrt(var + 1e-6));
    }
}

// ===========================================================================
// K2b: normalize -> tf32-rounded fp32, transpose into ynT32[m][row].
// ===========================================================================
__global__ void __launch_bounds__(256) k2b_normT(const float* __restrict__ sc,
                                                  const float* __restrict__ bi) {
    __shared__ float sh[64 * 65];
    int tid = threadIdx.x;
    int r0 = blockIdx.x * 64;
    float mu = g_stats[0], rs = g_stats[1];

    #pragma unroll
    for (int it = 0; it < 16; it++) {
        int idx = tid + it * 256;
        int r = idx >> 6, m = idx & 63;
        size_t gi = (size_t)(r0 + r) * 64 + m;
        float val = (g_y[gi] - mu) * rs * sc[gi] + bi[gi];
        uint32_t t;
        asm("cvt.rna.tf32.f32 %0, %1;" : "=r"(t) : "f"(val));
        sh[m * 65 + r] = __uint_as_float(t);
    }
    __syncthreads();

    int w = tid >> 5, lane = tid & 31;
    #pragma unroll 1
    for (int m = w; m < 64; m += 8) {
        float2 p;
        p.x = sh[m * 65 + lane * 2];
        p.y = sh[m * 65 + lane * 2 + 1];
        *((float2*)(g_ynT32 + (size_t)m * 8192 + r0) + lane) = p;
    }
}

// ===========================================================================
// tf32 mma helper
// ===========================================================================
__device__ __forceinline__ void mma1688(float* d, uint32_t a0, uint32_t a1,
                                        uint32_t a2, uint32_t a3,
                                        uint32_t b0, uint32_t b1) {
    asm volatile(
        "mma.sync.aligned.m16n8k8.row.col.f32.tf32.tf32.f32 "
        "{%0,%1,%2,%3}, {%4,%5,%6,%7}, {%8,%9}, {%0,%1,%2,%3};"
        : "+f"(d[0]), "+f"(d[1]), "+f"(d[2]), "+f"(d[3])
        : "r"(a0), "r"(a1), "r"(a2), "r"(a3), "r"(b0), "r"(b1));
}

// ===========================================================================
// K3: out_part[n,m] = sum_k ynT[m,k]*Co[k,n] via tf32 mma + cp.async.
// Grid (64 col-tiles x 128 n, 16 k-splits x 512). 128 threads, 4 CTAs/SM.
// Co streamed fp32 gmem->smem via cp.async.cg (no registers, no convert);
// fragments loaded with conflict-free LDS.32 (strides 136 / 36).
// Warp tile m64 x n32; per chunk: 4 ksteps x (8 B-lds + 4x(4 A-lds + 4 mma)).
// ===========================================================================
__global__ void __launch_bounds__(128, 4) k3_gemm(const float* __restrict__ Co) {
    extern __shared__ float smem[];
    float* co_s = smem;                       // [2][KC][CO32_LD]
    float* yn_s = smem + 2 * CO32_BUF;        // [2][64][YN32_LD]
    int tid = threadIdx.x, w = tid >> 5, lane = tid & 31;
    int colbase = blockIdx.x * 128;
    int k_org = blockIdx.y * KQ;

    uint32_t co_sb = (uint32_t)__cvta_generic_to_shared(co_s);
    uint32_t yn_sb = (uint32_t)__cvta_generic_to_shared(yn_s);

    int crow = tid >> 2, cseg = tid & 3;      // Co: k-row (0..31), 32-col segment
    int ymr = tid >> 1, yhalf = tid & 1;      // yn: m-row (0..63), 16-k half
    const float* csrc = Co + (size_t)(k_org + crow) * 8192 + colbase + cseg * 32;
    const float* ysrc = g_ynT32 + (size_t)ymr * 8192 + k_org + yhalf * 16;
    uint32_t cdst = co_sb + (uint32_t)(crow * CO32_LD + cseg * 32) * 4u;
    uint32_t ydst = yn_sb + (uint32_t)(ymr * YN32_LD + yhalf * 16) * 4u;

    auto PREFETCH = [&](int ch) {
        int buf = ch & 1;
        const float* cs = csrc + (size_t)ch * KC * 8192;
        uint32_t cd = cdst + (uint32_t)(buf * CO32_BUF) * 4u;
        #pragma unroll
        for (int j = 0; j < 8; j++)
            asm volatile("cp.async.cg.shared.global [%0], [%1], 16;"
                         :: "r"(cd + j * 16u), "l"(cs + j * 4) : "memory");
        const float* ys = ysrc + ch * KC;
        uint32_t yd = ydst + (uint32_t)(buf * YN32_BUF) * 4u;
        #pragma unroll
        for (int j = 0; j < 4; j++)
            asm volatile("cp.async.cg.shared.global [%0], [%1], 16;"
                         :: "r"(yd + j * 16u), "l"(ys + j * 4) : "memory");
    };

    float d[4][4][4];
    #pragma unroll
    for (int mt = 0; mt < 4; mt++)
        #pragma unroll
        for (int nt = 0; nt < 4; nt++)
            #pragma unroll
            for (int v = 0; v < 4; v++) d[mt][nt][v] = 0.f;

    PREFETCH(0);
    asm volatile("cp.async.commit_group;" ::: "memory");
    PREFETCH(1);
    asm volatile("cp.async.commit_group;" ::: "memory");

    int l4 = lane & 3, l8 = lane >> 2;

    #pragma unroll 1
    for (int ch = 0; ch < NCH; ch++) {
        asm volatile("cp.async.wait_group 1;" ::: "memory");
        __syncthreads();
        const float* cb = co_s + (ch & 1) * CO32_BUF;
        const float* yb = yn_s + (ch & 1) * YN32_BUF;

        #pragma unroll
        for (int ks = 0; ks < 4; ks++) {
            uint32_t b[4][2];
            #pragma unroll
            for (int nt = 0; nt < 4; nt++) {
                int col = w * 32 + nt * 8 + l8;
                b[nt][0] = __float_as_uint(cb[(ks * 8 + l4) * CO32_LD + col]);
                b[nt][1] = __float_as_uint(cb[(ks * 8 + 4 + l4) * CO32_LD + col]);
            }
            #pragma unroll
            for (int mt = 0; mt < 4; mt++) {
                int r = mt * 16 + l8, c = ks * 8 + l4;
                uint32_t a0 = __float_as_uint(yb[r * YN32_LD + c]);
                uint32_t a1 = __float_as_uint(yb[(r + 8) * YN32_LD + c]);
                uint32_t a2 = __float_as_uint(yb[r * YN32_LD + c + 4]);
                uint32_t a3 = __float_as_uint(yb[(r + 8) * YN32_LD + c + 4]);
                mma1688(d[mt][0], a0, a1, a2, a3, b[0][0], b[0][1]);
                mma1688(d[mt][1], a0, a1, a2, a3, b[1][0], b[1][1]);
                mma1688(d[mt][2], a0, a1, a2, a3, b[2][0], b[2][1]);
                mma1688(d[mt][3], a0, a1, a2, a3, b[3][0], b[3][1]);
            }
        }
        __syncthreads();
        if (ch + 2 < NCH) PREFETCH(ch + 2);
        asm volatile("cp.async.commit_group;" ::: "memory");
    }

    // epilogue: write k-split partial (D frag: rows l8/+8, cols 2*l4/+1)
    float* pb = g_part + (size_t)blockIdx.y * N_EL;
    int er = l8, ec = l4 * 2;
    #pragma unroll
    for (int mt = 0; mt < 4; mt++) {
        #pragma unroll
        for (int nt = 0; nt < 4; nt++) {
            int n = colbase + w * 32 + nt * 8 + ec;
            int m = mt * 16 + er;
            pb[(size_t)n * 64 + m]           = d[mt][nt][0];
            pb[(size_t)(n + 1) * 64 + m]     = d[mt][nt][1];
            pb[(size_t)n * 64 + m + 8]       = d[mt][nt][2];
            pb[(size_t)(n + 1) * 64 + m + 8] = d[mt][nt][3];
        }
    }
}

// ===========================================================================
// K4: out = sum of 16 k-split partials (float4)
// ===========================================================================
__global__ void __launch_bounds__(256) k4_reduce(float* __restrict__ out) {
    int idx = blockIdx.x * 256 + threadIdx.x;
    float4 a = ((const float4*)g_part)[idx];
    #pragma unroll
    for (int s = 1; s < KSPLIT; s++) {
        float4 b = ((const float4*)(g_part + (size_t)s * N_EL))[idx];
        a.x += b.x; a.y += b.y; a.z += b.z; a.w += b.w;
    }
    ((float4*)out)[idx] = a;
}

extern "C" void kernel_launch(void* const* d_in, const int* in_sizes, int n_in,
                              void* d_out, int out_size) {
    const float* x  = (const float*)d_in[0];
    const float* Wi = (const float*)d_in[1];
    const float* sc = (const float*)d_in[2];
    const float* bi = (const float*)d_in[3];
    const float* Co = (const float*)d_in[4];
    float* out = (float*)d_out;

    cudaFuncSetAttribute(k3_gemm, cudaFuncAttributeMaxDynamicSharedMemorySize, K3_SMEM);

    k1_capsule<<<N_CI, 256>>>(x, Wi);
    k2_stats<<<1, 256>>>();
    k2b_normT<<<128, 256>>>(sc, bi);
    dim3 g3(64, KSPLIT);
    k3_gemm<<<g3, 128, K3_SMEM>>>(Co);
    k4_reduce<<<512, 256>>>(out);
}